// round 16
// baseline (speedup 1.0000x reference)
#include <cuda_runtime.h>
#include <cstdint>
#include <math.h>

#define NB 2
#define NT 1024
#define NC 1024
#define NH 16
#define NNh 64
#define NBT (NB*NT)
#define CH 16
#define NCH (NT/CH)
#define KSMAX 8

// ---------------- scratch (device globals; no allocation allowed) ----------------
__device__ float g_mixh[NBT*128];
__device__ float g_xrg[NBT*NC];
__device__ float g_xwa[NBT*NC];
__device__ float g_xk [NBT*NC];
__device__ float g_xv [NBT*NC];
__device__ float g_r  [NBT*NC];
__device__ float g_k  [NBT*NC];
__device__ float g_v  [NBT*NC];
__device__ float g_w1t[NBT*64];
__device__ float g_a1 [NBT*16];
__device__ float g_ma1[NBT*16];
__device__ float g_kk1[NBT*16];
__device__ float g_mk1[NBT*16];
__device__ float g_g1 [NBT*128];
__device__ float g_g  [NBT*NC];
__device__ float g_ew [NBT*NC];
__device__ float g_kf [NBT*NC];
__device__ float g_kkn[NBT*NC];
__device__ float g_bb [NBT*NC];
__device__ float g_y  [NBT*NC];
__device__ float g_z  [NBT*NC];
__device__ float g_dw [NBT*NC];
__device__ float g_da [NBT*NC];
__device__ float g_dma[NBT*NC];
__device__ float g_dkk[NBT*NC];
__device__ float g_dmk[NBT*NC];
__device__ float g_part[KSMAX*NBT*128];

// ---------------- packed f32x2 helpers ----------------
__device__ __forceinline__ unsigned long long pk2(float lo, float hi) {
    unsigned long long r;
    asm("mov.b64 %0, {%1, %2};" : "=l"(r) : "f"(lo), "f"(hi));
    return r;
}
__device__ __forceinline__ void fma2(unsigned long long& d, unsigned long long a, unsigned long long b) {
    asm("fma.rn.f32x2 %0, %1, %2, %0;" : "+l"(d) : "l"(a), "l"(b));
}
__device__ __forceinline__ unsigned long long mul2(unsigned long long a, unsigned long long b) {
    unsigned long long r;
    asm("mul.rn.f32x2 %0, %1, %2;" : "=l"(r) : "l"(a), "l"(b));
    return r;
}
__device__ __forceinline__ float2 up2(unsigned long long a) {
    float2 f;
    asm("mov.b64 {%0, %1}, %2;" : "=f"(f.x), "=f"(f.y) : "l"(a));
    return f;
}

// ---------------- shared GEMM body v2: 128x64 tile, 128 threads, 8m x 8n/thread ----
// Double-buffered. Per k-step: 4x LDS.128 + 8 pk2 + 32 FFMA2.
// mode 1 fuses token-shift mix epilogue.
__device__ __forceinline__ void gemm_body(
    const float* __restrict__ A, int lda,
    const float* __restrict__ W, int ldw,
    float* __restrict__ C, int K,
    const float* __restrict__ xin, const float* __restrict__ tmf, int mode)
{
    __shared__ __align__(16) float As[2][16][132];
    __shared__ __align__(16) float Ws[2][16][68];
    const int bm = blockIdx.y * 128;
    const int bn = blockIdx.x * 64;
    const int tid = threadIdx.x;         // 0..127
    const int tx = tid & 7;              // n-group of 8
    const int ty = tid >> 3;             // m-group of 8 (0..15)
    const int wr = tid >> 1;             // W loader row 0..63
    const int wka = (tid & 1) * 8;

    const float* Aptr = A + (size_t)(bm + tid)*lda;   // one full A row per thread
    const float* Wptr = W + (size_t)(bn + wr)*ldw + wka;

    unsigned long long acc[8][4];
    #pragma unroll
    for (int i = 0; i < 8; i++)
        #pragma unroll
        for (int j = 0; j < 4; j++) acc[i][j] = 0ull;

    // prologue: tile 0
    float4 a0 = *(const float4*)(Aptr);
    float4 a1 = *(const float4*)(Aptr + 4);
    float4 a2 = *(const float4*)(Aptr + 8);
    float4 a3 = *(const float4*)(Aptr + 12);
    float4 w0 = *(const float4*)(Wptr);
    float4 w1 = *(const float4*)(Wptr + 4);
    As[0][ 0][tid]=a0.x; As[0][ 1][tid]=a0.y; As[0][ 2][tid]=a0.z; As[0][ 3][tid]=a0.w;
    As[0][ 4][tid]=a1.x; As[0][ 5][tid]=a1.y; As[0][ 6][tid]=a1.z; As[0][ 7][tid]=a1.w;
    As[0][ 8][tid]=a2.x; As[0][ 9][tid]=a2.y; As[0][10][tid]=a2.z; As[0][11][tid]=a2.w;
    As[0][12][tid]=a3.x; As[0][13][tid]=a3.y; As[0][14][tid]=a3.z; As[0][15][tid]=a3.w;
    Ws[0][wka+0][wr]=w0.x; Ws[0][wka+1][wr]=w0.y; Ws[0][wka+2][wr]=w0.z; Ws[0][wka+3][wr]=w0.w;
    Ws[0][wka+4][wr]=w1.x; Ws[0][wka+5][wr]=w1.y; Ws[0][wka+6][wr]=w1.z; Ws[0][wka+7][wr]=w1.w;
    __syncthreads();

    const int NIT = K >> 4;
    for (int c = 0; c < NIT; c++) {
        const int cb = c & 1;
        if (c + 1 < NIT) {
            const int k0 = (c + 1) << 4;
            a0 = *(const float4*)(Aptr + k0);
            a1 = *(const float4*)(Aptr + k0 + 4);
            a2 = *(const float4*)(Aptr + k0 + 8);
            a3 = *(const float4*)(Aptr + k0 + 12);
            w0 = *(const float4*)(Wptr + k0);
            w1 = *(const float4*)(Wptr + k0 + 4);
        }
        #pragma unroll
        for (int kk = 0; kk < 16; kk++) {
            float4 f0 = *(const float4*)&As[cb][kk][ty*8];
            float4 f1 = *(const float4*)&As[cb][kk][ty*8+4];
            ulonglong2 q0 = *(const ulonglong2*)&Ws[cb][kk][tx*8];
            ulonglong2 q1 = *(const ulonglong2*)&Ws[cb][kk][tx*8+4];
            float a8[8] = {f0.x,f0.y,f0.z,f0.w,f1.x,f1.y,f1.z,f1.w};
            #pragma unroll
            for (int i = 0; i < 8; i++) {
                unsigned long long ad = pk2(a8[i], a8[i]);
                fma2(acc[i][0], ad, q0.x);
                fma2(acc[i][1], ad, q0.y);
                fma2(acc[i][2], ad, q1.x);
                fma2(acc[i][3], ad, q1.y);
            }
        }
        if (c + 1 < NIT) {
            const int nb = cb ^ 1;
            As[nb][ 0][tid]=a0.x; As[nb][ 1][tid]=a0.y; As[nb][ 2][tid]=a0.z; As[nb][ 3][tid]=a0.w;
            As[nb][ 4][tid]=a1.x; As[nb][ 5][tid]=a1.y; As[nb][ 6][tid]=a1.z; As[nb][ 7][tid]=a1.w;
            As[nb][ 8][tid]=a2.x; As[nb][ 9][tid]=a2.y; As[nb][10][tid]=a2.z; As[nb][11][tid]=a2.w;
            As[nb][12][tid]=a3.x; As[nb][13][tid]=a3.y; As[nb][14][tid]=a3.z; As[nb][15][tid]=a3.w;
            Ws[nb][wka+0][wr]=w0.x; Ws[nb][wka+1][wr]=w0.y; Ws[nb][wka+2][wr]=w0.z; Ws[nb][wka+3][wr]=w0.w;
            Ws[nb][wka+4][wr]=w1.x; Ws[nb][wka+5][wr]=w1.y; Ws[nb][wka+6][wr]=w1.z; Ws[nb][wka+7][wr]=w1.w;
        }
        __syncthreads();
    }

    const int n0 = bn + tx*8;
    #pragma unroll
    for (int i = 0; i < 8; i++) {
        const int m = bm + ty*8 + i;
        float2 c0 = up2(acc[i][0]);
        float2 c1 = up2(acc[i][1]);
        float2 c2 = up2(acc[i][2]);
        float2 c3 = up2(acc[i][3]);
        float4 o0 = make_float4(c0.x, c0.y, c1.x, c1.y);
        float4 o1 = make_float4(c2.x, c2.y, c3.x, c3.y);
        if (mode == 1) {
            const int tt = m & (NT-1);
            const float* xr = xin + (size_t)m*NC + n0;
            float4 xv0 = *(const float4*)xr;
            float4 xv1 = *(const float4*)(xr + 4);
            float4 xp0 = make_float4(0.f,0.f,0.f,0.f);
            float4 xp1 = make_float4(0.f,0.f,0.f,0.f);
            if (tt != 0) { xp0 = *(const float4*)(xr - NC); xp1 = *(const float4*)(xr - NC + 4); }
            float4 t0 = *(const float4*)(tmf + n0);
            float4 t1 = *(const float4*)(tmf + n0 + 4);
            o0.x = fmaf(xp0.x - xv0.x, t0.x + o0.x, xv0.x);
            o0.y = fmaf(xp0.y - xv0.y, t0.y + o0.y, xv0.y);
            o0.z = fmaf(xp0.z - xv0.z, t0.z + o0.z, xv0.z);
            o0.w = fmaf(xp0.w - xv0.w, t0.w + o0.w, xv0.w);
            o1.x = fmaf(xp1.x - xv1.x, t1.x + o1.x, xv1.x);
            o1.y = fmaf(xp1.y - xv1.y, t1.y + o1.y, xv1.y);
            o1.z = fmaf(xp1.z - xv1.z, t1.z + o1.z, xv1.z);
            o1.w = fmaf(xp1.w - xv1.w, t1.w + o1.w, xv1.w);
        }
        *(float4*)(C + (size_t)m*NC + n0)     = o0;
        *(float4*)(C + (size_t)m*NC + n0 + 4) = o1;
    }
}

__global__ __launch_bounds__(128, 4) void gemm_big_kernel(
    const float* __restrict__ A, int lda,
    const float* __restrict__ W, int ldw,
    float* __restrict__ C, int K)
{
    gemm_body(A, lda, W, ldw, C, K, 0, 0, 0);
}

__global__ __launch_bounds__(128, 4) void gemm_rkv_kernel(
    const float* __restrict__ A0, const float* __restrict__ A1, const float* __restrict__ A2,
    const float* __restrict__ W0, const float* __restrict__ W1, const float* __restrict__ W2,
    float* __restrict__ C0, float* __restrict__ C1, float* __restrict__ C2)
{
    const int z = blockIdx.z;
    const float* A = (z == 0) ? A0 : (z == 1) ? A1 : A2;
    const float* W = (z == 0) ? W0 : (z == 1) ? W1 : W2;
    float*       C = (z == 0) ? C0 : (z == 1) ? C1 : C2;
    gemm_body(A, NC, W, NC, C, NC, 0, 0, 0);
}

__global__ __launch_bounds__(128, 4) void gemm_mix4_kernel(
    const float* __restrict__ mixh, const float* __restrict__ maaw2,
    float* __restrict__ C0, float* __restrict__ C1,
    float* __restrict__ C2, float* __restrict__ C3,
    const float* __restrict__ x, const float* __restrict__ tm)
{
    const int z = blockIdx.z;
    float* C = (z == 0) ? C0 : (z == 1) ? C1 : (z == 2) ? C2 : C3;
    gemm_body(mixh + z*32, 128, maaw2 + (size_t)z*NC*32, 32, C, 32, x, tm + z*NC, 1);
}

__global__ __launch_bounds__(128, 4) void gemm_d4_kernel(
    const float* __restrict__ A0, const float* __restrict__ A1,
    const float* __restrict__ A2, const float* __restrict__ A3,
    const float* __restrict__ W0, const float* __restrict__ W1,
    const float* __restrict__ W2, const float* __restrict__ W3,
    float* __restrict__ C0, float* __restrict__ C1,
    float* __restrict__ C2, float* __restrict__ C3)
{
    const int z = blockIdx.z;
    const float* A = (z == 0) ? A0 : (z == 1) ? A1 : (z == 2) ? A2 : A3;
    const float* W = (z == 0) ? W0 : (z == 1) ? W1 : (z == 2) ? W2 : W3;
    float*       C = (z == 0) ? C0 : (z == 1) ? C1 : (z == 2) ? C2 : C3;
    gemm_body(A, 16, W, 16, C, 16, 0, 0, 0);
}

// ---------------- LORA GEMM v2: register-blocked 64x32 tile, K-split -------------
__global__ __launch_bounds__(128) void lora_kernel(
    const float* __restrict__ A,
    const float* __restrict__ W0, const float* __restrict__ W1, const float* __restrict__ W2,
    int nb0, int nb1,
    float* __restrict__ part, int N, int K, int ks,
    int smode, const float* __restrict__ tmx)
{
    __shared__ __align__(16) float As[32][68];
    __shared__ __align__(16) float Ws[32][36];
    const int bm = blockIdx.x * 64;
    const int bn = blockIdx.y * 32;
    const int kb = blockIdx.z;
    const int klen = K / ks;
    const int kbeg = kb * klen;
    const int tid = threadIdx.x;
    const int ty = tid >> 3;
    const int tx = tid & 7;

    float acc[4][4];
    #pragma unroll
    for (int i = 0; i < 4; i++)
        #pragma unroll
        for (int j = 0; j < 4; j++) acc[i][j] = 0.f;

    for (int k0 = kbeg; k0 < kbeg + klen; k0 += 32) {
        #pragma unroll
        for (int i = 0; i < 4; i++) {
            const int idx = tid + i*128;
            const int row = idx >> 3;
            const int kq  = idx & 7;
            float4 av;
            if (smode) {
                const int m = bm + row;
                const int tt = m & (NT-1);
                const float* xr = A + (size_t)m*K + k0 + kq*4;
                float4 xv4 = *(const float4*)xr;
                float4 xp4 = make_float4(0.f,0.f,0.f,0.f);
                if (tt != 0) xp4 = *(const float4*)(xr - K);
                float4 t4 = *(const float4*)(tmx + k0 + kq*4);
                av.x = fmaf(xp4.x - xv4.x, t4.x, xv4.x);
                av.y = fmaf(xp4.y - xv4.y, t4.y, xv4.y);
                av.z = fmaf(xp4.z - xv4.z, t4.z, xv4.z);
                av.w = fmaf(xp4.w - xv4.w, t4.w, xv4.w);
            } else {
                av = *(const float4*)(A + (size_t)(bm+row)*K + k0 + kq*4);
            }
            As[kq*4+0][row]=av.x; As[kq*4+1][row]=av.y;
            As[kq*4+2][row]=av.z; As[kq*4+3][row]=av.w;
        }
        #pragma unroll
        for (int i = 0; i < 2; i++) {
            const int idx = tid + i*128;
            const int row = idx >> 3;
            const int kq  = idx & 7;
            const int wrow = bn + row;
            const float* wp;
            if (wrow < nb0)      wp = W0 + (size_t)wrow*K;
            else if (wrow < nb1) wp = W1 + (size_t)(wrow - nb0)*K;
            else                 wp = W2 + (size_t)(wrow - nb1)*K;
            float4 wv = *(const float4*)(wp + k0 + kq*4);
            Ws[kq*4+0][row]=wv.x; Ws[kq*4+1][row]=wv.y;
            Ws[kq*4+2][row]=wv.z; Ws[kq*4+3][row]=wv.w;
        }
        __syncthreads();
        #pragma unroll
        for (int kk = 0; kk < 32; kk++) {
            float4 a4 = *(const float4*)&As[kk][ty*4];
            float4 w4 = *(const float4*)&Ws[kk][tx*4];
            float am[4] = {a4.x, a4.y, a4.z, a4.w};
            #pragma unroll
            for (int i = 0; i < 4; i++) {
                acc[i][0] = fmaf(am[i], w4.x, acc[i][0]);
                acc[i][1] = fmaf(am[i], w4.y, acc[i][1]);
                acc[i][2] = fmaf(am[i], w4.z, acc[i][2]);
                acc[i][3] = fmaf(am[i], w4.w, acc[i][3]);
            }
        }
        __syncthreads();
    }
    const int n0 = bn + tx*4;
    #pragma unroll
    for (int i = 0; i < 4; i++) {
        const int m = bm + ty*4 + i;
        float* pr = part + ((size_t)kb*NBT + m)*N;
        *(float4*)(pr + n0) = make_float4(acc[i][0], acc[i][1], acc[i][2], acc[i][3]);
    }
}

__global__ __launch_bounds__(256) void lora_reduce_kernel(
    const float* __restrict__ part, int N, int ks,
    float* __restrict__ d0, int n0, int act0,
    float* __restrict__ d1, int n1, int act1,
    float* __restrict__ d2, int n2, int act2)
{
    const int idx = blockIdx.x*256 + threadIdx.x;
    const int n4 = N >> 2;
    const int m = idx / n4;
    const int c = (idx - m*n4) << 2;
    float4 s = make_float4(0.f,0.f,0.f,0.f);
    for (int z = 0; z < ks; z++) {
        float4 p = *(const float4*)(part + ((size_t)z*NBT + m)*N + c);
        s.x += p.x; s.y += p.y; s.z += p.z; s.w += p.w;
    }
    float* d; int act;
    if (c < n0)           { d = d0 + (size_t)m*n0 + c;            act = act0; }
    else if (c < n0 + n1) { d = d1 + (size_t)m*n1 + (c - n0);     act = act1; }
    else                  { d = d2 + (size_t)m*n2 + (c - n0 - n1); act = act2; }
    if (act) { s.x = tanhf(s.x); s.y = tanhf(s.y); s.z = tanhf(s.z); s.w = tanhf(s.w); }
    *(float4*)d = s;
}

// ---------------- post ----------------
__global__ __launch_bounds__(256) void post_kernel(
    const float* __restrict__ td,  const float* __restrict__ ta5,
    const float* __restrict__ tma_, const float* __restrict__ tmk_)
{
    const int tok = blockIdx.x;
    const int tid = threadIdx.x;
    const size_t base = (size_t)tok*NC;
    const int c = tid * 4;
    float4 kraw = *(const float4*)(g_k   + base + c);
    float4 dw4  = *(const float4*)(g_dw  + base + c);
    float4 da4  = *(const float4*)(g_da  + base + c);
    float4 dma4 = *(const float4*)(g_dma + base + c);
    float4 dkk4 = *(const float4*)(g_dkk + base + c);
    float4 dmk4 = *(const float4*)(g_dmk + base + c);
    float4 td4  = *(const float4*)(td   + c);
    float4 ta4  = *(const float4*)(ta5  + c);
    float4 tm4  = *(const float4*)(tma_ + c);
    float4 tk4  = *(const float4*)(tmk_ + c);

    float kr[4] = {kraw.x, kraw.y, kraw.z, kraw.w};
    float uw[4] = {td4.x+dw4.x, td4.y+dw4.y, td4.z+dw4.z, td4.w+dw4.w};
    float ua[4] = {ta4.x+da4.x, ta4.y+da4.y, ta4.z+da4.z, ta4.w+da4.w};
    float um[4] = {tm4.x+dma4.x, tm4.y+dma4.y, tm4.z+dma4.z, tm4.w+dma4.w};
    float uk[4] = {tk4.x+dmk4.x, tk4.y+dmk4.y, tk4.z+dmk4.z, tk4.w+dmk4.w};
    float kkq[4] = {kr[0]+dkk4.x, kr[1]+dkk4.y, kr[2]+dkk4.z, kr[3]+dkk4.w};

    float ewv[4], kfv[4], avv[4];
    float ss = 0.f;
    #pragma unroll
    for (int q = 0; q < 4; q++) {
        float spz = -uw[q];
        float sp = (spz > 15.f) ? spz : log1pf(expf(spz));
        float w = -sp - 0.5f;
        ewv[q] = expf(w);
        float a  = 1.f/(1.f + expf(-ua[q]));
        float ma = 1.f/(1.f + expf(-um[q]));
        float mk = 1.f/(1.f + expf(-uk[q]));
        avv[q] = a;
        kfv[q] = kr[q] * (ma + a*(1.f - ma)) * expf(w*mk);
        ss = fmaf(kkq[q], kkq[q], ss);
    }
    ss += __shfl_xor_sync(0xffffffffu, ss, 1);
    ss += __shfl_xor_sync(0xffffffffu, ss, 2);
    ss += __shfl_xor_sync(0xffffffffu, ss, 4);
    ss += __shfl_xor_sync(0xffffffffu, ss, 8);
    const float rinv = 1.f / fmaxf(sqrtf(ss), 1e-12f);
    float4 kkn4, bb4, ew4, kf4;
    kkn4.x = kkq[0]*rinv; kkn4.y = kkq[1]*rinv; kkn4.z = kkq[2]*rinv; kkn4.w = kkq[3]*rinv;
    bb4.x = -kkn4.x*avv[0]; bb4.y = -kkn4.y*avv[1]; bb4.z = -kkn4.z*avv[2]; bb4.w = -kkn4.w*avv[3];
    ew4.x = ewv[0]; ew4.y = ewv[1]; ew4.z = ewv[2]; ew4.w = ewv[3];
    kf4.x = kfv[0]; kf4.y = kfv[1]; kf4.z = kfv[2]; kf4.w = kfv[3];
    *(float4*)(g_kkn + base + c) = kkn4;
    *(float4*)(g_bb  + base + c) = bb4;
    *(float4*)(g_ew  + base + c) = ew4;
    *(float4*)(g_kf  + base + c) = kf4;
}

// ---------------- RWKV-7 scan ----------------
#define LOAD_ARR(arr, G) { \
    const int i0 = tid, i1 = tid + 128; \
    pf[2*(arr)+0] = *(const float4*)((G) + gb + (size_t)(i0>>4)*NC + ((i0&15)<<2)); \
    pf[2*(arr)+1] = *(const float4*)((G) + gb + (size_t)(i1>>4)*NC + ((i1&15)<<2)); }
#define STORE_ARR(arr, dst) { \
    const int i0 = tid, i1 = tid + 128; \
    *(float4*)&cbuf[dst][arr][i0>>4][(i0&15)<<2] = pf[2*(arr)+0]; \
    *(float4*)&cbuf[dst][arr][i1>>4][(i1&15)<<2] = pf[2*(arr)+1]; }

__global__ __launch_bounds__(128) void scan_kernel()
{
    const int blk = blockIdx.x;
    const int bh  = blk >> 1;
    const int rh  = blk & 1;
    const int b   = bh >> 4;
    const int h   = bh & 15;
    const int tid = threadIdx.x;
    const int row = rh*32 + (tid >> 2);
    const int sub = tid & 3;
    const int coff = sub * 16;

    __shared__ __align__(16) float cbuf[2][6][CH][64];

    unsigned long long S[8];
    #pragma unroll
    for (int j = 0; j < 8; j++) S[j] = 0ull;

    const size_t base = ((size_t)b*NT)*NC + (size_t)h*NNh;

    {
        const size_t gb = base;
        float4 pf[12];
        LOAD_ARR(0, g_r);  LOAD_ARR(1, g_ew); LOAD_ARR(2, g_kf);
        LOAD_ARR(3, g_v);  LOAD_ARR(4, g_kkn); LOAD_ARR(5, g_bb);
        STORE_ARR(0, 0); STORE_ARR(1, 0); STORE_ARR(2, 0);
        STORE_ARR(3, 0); STORE_ARR(4, 0); STORE_ARR(5, 0);
    }
    __syncthreads();

    for (int c = 0; c < NCH; c++) {
        const int buf = c & 1;
        const int nb  = buf ^ 1;
        float4 pf[12];
        if (c + 1 < NCH) {
            const size_t gb = base + (size_t)((c+1)*CH)*NC;
            LOAD_ARR(0, g_r);  LOAD_ARR(1, g_ew); LOAD_ARR(2, g_kf);
            LOAD_ARR(3, g_v);  LOAD_ARR(4, g_kkn); LOAD_ARR(5, g_bb);
        }
        const size_t ybase = base + (size_t)(c*CH)*NC + row;
        #pragma unroll 4
        for (int s = 0; s < CH; s++) {
            const ulonglong2* rp  = (const ulonglong2*)&cbuf[buf][0][s][coff];
            const ulonglong2* ewp = (const ulonglong2*)&cbuf[buf][1][s][coff];
            const ulonglong2* kfp = (const ulonglong2*)&cbuf[buf][2][s][coff];
            const ulonglong2* kkp = (const ulonglong2*)&cbuf[buf][4][s][coff];
            const ulonglong2* bbp = (const ulonglong2*)&cbuf[buf][5][s][coff];
            const float vv = cbuf[buf][3][s][row];
            unsigned long long a0 = 0ull, a1 = 0ull;
            #pragma unroll
            for (int j = 0; j < 4; j++) {
                ulonglong2 kq = kkp[j];
                fma2(a0, S[2*j+0], kq.x);
                fma2(a1, S[2*j+1], kq.y);
            }
            float2 fa0 = up2(a0), fa1 = up2(a1);
            float sab = (fa0.x + fa0.y) + (fa1.x + fa1.y);
            sab += __shfl_xor_sync(0xffffffffu, sab, 1);
            sab += __shfl_xor_sync(0xffffffffu, sab, 2);
            const unsigned long long sab2 = pk2(sab, sab);
            const unsigned long long vv2  = pk2(vv, vv);
            unsigned long long y0 = 0ull, y1 = 0ull;
            #pragma unroll
            for (int j = 0; j < 4; j++) {
                ulonglong2 eq = ewp[j], bq = bbp[j], kq = kfp[j], rq = rp[j];
                unsigned long long t0 = mul2(S[2*j+0], eq.x);
                fma2(t0, sab2, bq.x);
                fma2(t0, vv2,  kq.x);
                S[2*j+0] = t0;
                fma2(y0, t0, rq.x);
                unsigned long long t1 = mul2(S[2*j+1], eq.y);
                fma2(t1, sab2, bq.y);
                fma2(t1, vv2,  kq.y);
                S[2*j+1] = t1;
                fma2(y1, t1, rq.y);
            }
            float2 fy0 = up2(y0), fy1 = up2(y1);
            float yv = (fy0.x + fy0.y) + (fy1.x + fy1.y);
            yv += __shfl_xor_sync(0xffffffffu, yv, 1);
            yv += __shfl_xor_sync(0xffffffffu, yv, 2);
            if (sub == 0) g_y[ybase + (size_t)s*NC] = yv;
        }
        if (c + 1 < NCH) {
            STORE_ARR(0, nb); STORE_ARR(1, nb); STORE_ARR(2, nb);
            STORE_ARR(3, nb); STORE_ARR(4, nb); STORE_ARR(5, nb);
        }
        __syncthreads();
    }
}

// ---------------- tail ----------------
__global__ __launch_bounds__(256) void tail_kernel(
    const float* __restrict__ lnw, const float* __restrict__ lnb,
    const float* __restrict__ faaaa)
{
    const int tok = blockIdx.x;
    const int tid = threadIdx.x;
    const size_t base = (size_t)tok*NC;
    float yv[4], vv[4];
    float sy=0.f, syy=0.f, srk=0.f;
    #pragma unroll
    for (int q = 0; q < 4; q++) {
        const int c = tid*4 + q;
        float y = g_y[base+c];
        float r = g_r[base+c];
        float k = g_kf[base+c];
        vv[q] = g_v[base+c];
        yv[q] = y;
        sy += y;
        syy = fmaf(y, y, syy);
        srk = fmaf(r*k, faaaa[c], srk);
    }
    #pragma unroll
    for (int o = 1; o < 16; o <<= 1) {
        sy  += __shfl_xor_sync(0xffffffffu, sy,  o);
        syy += __shfl_xor_sync(0xffffffffu, syy, o);
        srk += __shfl_xor_sync(0xffffffffu, srk, o);
    }
    const float mu  = sy * (1.f/64.f);
    const float var = syy * (1.f/64.f) - mu*mu;
    const float inv = 1.f / sqrtf(var + 0.00064f);
    #pragma unroll
    for (int q = 0; q < 4; q++) {
        const int c = tid*4 + q;
        float yn = (yv[q] - mu) * inv * lnw[c] + lnb[c];
        g_z[base+c] = (yn + srk*vv[q]) * g_g[base+c];
    }
}

// ---------------- host ----------------
static inline void launch_big(const float* A, int lda, const float* W, int ldw,
                              float* C, int M, int K)
{
    dim3 grid(NC/64, M/128);
    gemm_big_kernel<<<grid, 128>>>(A, lda, W, ldw, C, K);
}
static inline void launch_lora(const float* A,
                               const float* W0, const float* W1, const float* W2,
                               int nb0, int nb1, float* part, int N, int K, int ks,
                               int smode, const float* tmx)
{
    dim3 grid(NBT/64, N/32, ks);
    lora_kernel<<<grid, 128>>>(A, W0, W1, W2, nb0, nb1, part, N, K, ks, smode, tmx);
}
static inline void launch_reduce(const float* part, int N, int ks,
                                 float* d0, int n0, int a0,
                                 float* d1, int n1, int a1,
                                 float* d2, int n2, int a2)
{
    lora_reduce_kernel<<<(NBT*N/4)/256, 256>>>(part, N, ks, d0, n0, a0, d1, n1, a1, d2, n2, a2);
}

extern "C" void kernel_launch(void* const* d_in, const int* in_sizes, int n_in,
                              void* d_out, int out_size)
{
    const float* x     = (const float*)d_in[0];
    const float* tmx   = (const float*)d_in[1];
    const float* tm    = (const float*)d_in[2];
    const float* maaw1 = (const float*)d_in[3];
    const float* maaw2 = (const float*)d_in[4];
    const float* td    = (const float*)d_in[5];
    const float* tdw1  = (const float*)d_in[6];
    const float* tdw2  = (const float*)d_in[7];
    const float* ta5   = (const float*)d_in[8];
    const float* taw1  = (const float*)d_in[9];
    const float* taw2  = (const float*)d_in[10];
    const float* tkw1  = (const float*)d_in[11];
    const float* tkw2  = (const float*)d_in[12];
    const float* gw1   = (const float*)d_in[13];
    const float* gw2   = (const float*)d_in[14];
    const float* tma_  = (const float*)d_in[15];
    const float* maw1  = (const float*)d_in[16];
    const float* maw2  = (const float*)d_in[17];
    const float* tmk_  = (const float*)d_in[18];
    const float* mkw1  = (const float*)d_in[19];
    const float* mkw2  = (const float*)d_in[20];
    const float* recw  = (const float*)d_in[21];
    const float* keyw  = (const float*)d_in[22];
    const float* valw  = (const float*)d_in[23];
    const float* outw  = (const float*)d_in[24];
    const float* lnw   = (const float*)d_in[25];
    const float* lnb   = (const float*)d_in[26];
    const float* faaaa = (const float*)d_in[27];
    float* out = (float*)d_out;

    float *p_mixh, *p_xrg, *p_xwa, *p_xk, *p_xv;
    float *p_r, *p_k, *p_v, *p_w1t, *p_a1, *p_ma1, *p_kk1, *p_mk1, *p_g1, *p_g, *p_z;
    float *p_dw, *p_da, *p_dma, *p_dkk, *p_dmk, *p_part;
    cudaGetSymbolAddress((void**)&p_mixh, g_mixh);
    cudaGetSymbolAddress((void**)&p_xrg,  g_xrg);
    cudaGetSymbolAddress((void**)&p_xwa,  g_xwa);
    cudaGetSymbolAddress((void**)&p_xk,   g_xk);
    cudaGetSymbolAddress((void**)&p_xv,   g_xv);
    cudaGetSymbolAddress((void**)&p_r,    g_r);
    cudaGetSymbolAddress((void**)&p_k,    g_k);
    cudaGetSymbolAddress((void**)&p_v,    g_v);
    cudaGetSymbolAddress((void**)&p_w1t,  g_w1t);
    cudaGetSymbolAddress((void**)&p_a1,   g_a1);
    cudaGetSymbolAddress((void**)&p_ma1,  g_ma1);
    cudaGetSymbolAddress((void**)&p_kk1,  g_kk1);
    cudaGetSymbolAddress((void**)&p_mk1,  g_mk1);
    cudaGetSymbolAddress((void**)&p_g1,   g_g1);
    cudaGetSymbolAddress((void**)&p_g,    g_g);
    cudaGetSymbolAddress((void**)&p_z,    g_z);
    cudaGetSymbolAddress((void**)&p_dw,   g_dw);
    cudaGetSymbolAddress((void**)&p_da,   g_da);
    cudaGetSymbolAddress((void**)&p_dma,  g_dma);
    cudaGetSymbolAddress((void**)&p_dkk,  g_dkk);
    cudaGetSymbolAddress((void**)&p_dmk,  g_dmk);
    cudaGetSymbolAddress((void**)&p_part, g_part);

    // 1. mix hidden: K-split lora + reduce(tanh)  (token shift fused into A-load)
    launch_lora(x, maaw1, maaw1, maaw1, 128, 128, p_part, 128, NC, 4, 1, tmx);
    launch_reduce(p_part, 128, 4, p_mixh, 128, 1, p_mixh, 0, 0, p_mixh, 0, 0);
    // 2. merged 4-way mixing (K=32, fused shift epilogue)
    {
        dim3 grid(NC/64, NBT/128, 4);
        gemm_mix4_kernel<<<grid, 128>>>(p_mixh, maaw2, p_xrg, p_xwa, p_xk, p_xv, x, tm);
    }
    // 3. xwa-cat LoRA hiddens: [w1t(64,tanh) | a1(16) | ma1(16)]
    launch_lora(p_xwa, tdw1, taw1, maw1, 64, 80, p_part, 96, NC, 4, 0, 0);
    launch_reduce(p_part, 96, 4, p_w1t, 64, 1, p_a1, 16, 0, p_ma1, 16, 0);
    // 4. merged r/k/v projections (K=1024)
    {
        dim3 grid(NC/64, NBT/128, 3);
        gemm_rkv_kernel<<<grid, 128>>>(p_xrg, p_xk, p_xv, recw, keyw, valw, p_r, p_k, p_v);
    }
    // 5. xk-cat LoRA hiddens: [kk1(16,tanh) | mk1(16)]  (ks=8: skinny)
    launch_lora(p_xk, tkw1, mkw1, mkw1, 16, 32, p_part, 32, NC, 8, 0, 0);
    launch_reduce(p_part, 32, 8, p_kk1, 16, 1, p_mk1, 16, 0, p_mk1, 0, 0);
    // 6. gate hidden g1 (N=128, tanh)
    launch_lora(p_xrg, gw1, gw1, gw1, 128, 128, p_part, 128, NC, 4, 0, 0);
    launch_reduce(p_part, 128, 4, p_g1, 128, 1, p_g1, 0, 0, p_g1, 0, 0);
    // 7. gate g = g1 @ gate_w2^T (K=128)
    launch_big(p_g1, 128, gw2, 128, p_g, NBT, 128);
    // 8. dw (K=64)
    launch_big(p_w1t, 64, tdw2, 64, p_dw, NBT, 64);
    // 9. merged 4x K=16 delta GEMMs
    {
        dim3 grid(NC/64, NBT/128, 4);
        gemm_d4_kernel<<<grid, 128>>>(p_a1, p_ma1, p_kk1, p_mk1,
                                      taw2, maw2, tkw2, mkw2,
                                      p_da, p_dma, p_dkk, p_dmk);
    }
    // 10. elementwise post
    post_kernel<<<NBT, 256>>>(td, ta5, tma_, tmk_);
    // 11. RWKV-7 scan
    scan_kernel<<<NB*NH*2, 128>>>();
    // 12. GroupNorm + bonus + gate
    tail_kernel<<<NBT, 256>>>(lnw, lnb, faaaa);
    // 13. output projection
    launch_big(p_z, NC, outw, NC, out, NBT, NC);

    (void)in_sizes; (void)n_in; (void)out_size; (void)tdw1;
}

// round 17
// speedup vs baseline: 1.1352x; 1.1352x over previous
#include <cuda_runtime.h>
#include <cstdint>
#include <math.h>

#define NB 2
#define NT 1024
#define NC 1024
#define NH 16
#define NNh 64
#define NBT (NB*NT)
#define CH 16
#define NCH (NT/CH)
#define KSMAX 8

// ---------------- scratch (device globals; no allocation allowed) ----------------
__device__ float g_mixh[NBT*128];
__device__ float g_xrg[NBT*NC];
__device__ float g_xwa[NBT*NC];
__device__ float g_xk [NBT*NC];
__device__ float g_xv [NBT*NC];
__device__ float g_r  [NBT*NC];
__device__ float g_k  [NBT*NC];
__device__ float g_v  [NBT*NC];
__device__ float g_w1t[NBT*64];
__device__ float g_a1 [NBT*16];
__device__ float g_ma1[NBT*16];
__device__ float g_kk1[NBT*16];
__device__ float g_mk1[NBT*16];
__device__ float g_g1 [NBT*128];
__device__ float g_g  [NBT*NC];
__device__ float g_ew [NBT*NC];
__device__ float g_kf [NBT*NC];
__device__ float g_kkn[NBT*NC];
__device__ float g_bb [NBT*NC];
__device__ float g_y  [NBT*NC];
__device__ float g_z  [NBT*NC];
__device__ float g_dw [NBT*NC];
__device__ float g_da [NBT*NC];
__device__ float g_dma[NBT*NC];
__device__ float g_dkk[NBT*NC];
__device__ float g_dmk[NBT*NC];
__device__ float g_part[KSMAX*NBT*128];   // K-split partials (max N=128)

// ---------------- packed f32x2 helpers ----------------
__device__ __forceinline__ unsigned long long pk2(float lo, float hi) {
    unsigned long long r;
    asm("mov.b64 %0, {%1, %2};" : "=l"(r) : "f"(lo), "f"(hi));
    return r;
}
__device__ __forceinline__ void fma2(unsigned long long& d, unsigned long long a, unsigned long long b) {
    asm("fma.rn.f32x2 %0, %1, %2, %0;" : "+l"(d) : "l"(a), "l"(b));
}
__device__ __forceinline__ unsigned long long mul2(unsigned long long a, unsigned long long b) {
    unsigned long long r;
    asm("mul.rn.f32x2 %0, %1, %2;" : "=l"(r) : "l"(a), "l"(b));
    return r;
}
__device__ __forceinline__ float2 up2(unsigned long long a) {
    float2 f;
    asm("mov.b64 {%0, %1}, %2;" : "=f"(f.x), "=f"(f.y) : "l"(a));
    return f;
}

// ---------------- shared GEMM body (R9/R15-winning double-buffered structure) -----
__device__ __forceinline__ void gemm_body(
    const float* __restrict__ A, int lda,
    const float* __restrict__ W, int ldw,
    float* __restrict__ C, int K,
    const float* __restrict__ xin, const float* __restrict__ tmf, int mode)
{
    __shared__ __align__(16) float As[2][16][132];
    __shared__ __align__(16) float Ws[2][16][68];
    const int bm = blockIdx.y * 128;
    const int bn = blockIdx.x * 64;
    const int tid = threadIdx.x;
    const int tx = tid & 15;
    const int ty = tid >> 4;
    const int lr = tid >> 1;
    const int lka = (tid & 1) * 8;
    const int wr = tid >> 2;
    const int wka = (tid & 3) * 4;

    const float* Aptr = A + (size_t)(bm + lr)*lda + lka;
    const float* Wptr = W + (size_t)(bn + wr)*ldw + wka;

    unsigned long long acc[8][2];
    #pragma unroll
    for (int i = 0; i < 8; i++) { acc[i][0] = 0ull; acc[i][1] = 0ull; }

    float4 a0 = *(const float4*)(Aptr);
    float4 a1 = *(const float4*)(Aptr + 4);
    float4 wv = *(const float4*)(Wptr);
    As[0][lka+0][lr]=a0.x; As[0][lka+1][lr]=a0.y; As[0][lka+2][lr]=a0.z; As[0][lka+3][lr]=a0.w;
    As[0][lka+4][lr]=a1.x; As[0][lka+5][lr]=a1.y; As[0][lka+6][lr]=a1.z; As[0][lka+7][lr]=a1.w;
    Ws[0][wka+0][wr]=wv.x; Ws[0][wka+1][wr]=wv.y; Ws[0][wka+2][wr]=wv.z; Ws[0][wka+3][wr]=wv.w;
    __syncthreads();

    const int NIT = K >> 4;
    for (int c = 0; c < NIT; c++) {
        const int cb = c & 1;
        if (c + 1 < NIT) {
            const int k0 = (c + 1) << 4;
            a0 = *(const float4*)(Aptr + k0);
            a1 = *(const float4*)(Aptr + k0 + 4);
            wv = *(const float4*)(Wptr + k0);
        }
        #pragma unroll
        for (int kk = 0; kk < 16; kk++) {
            float4 f0 = *(const float4*)&As[cb][kk][ty*8];
            float4 f1 = *(const float4*)&As[cb][kk][ty*8+4];
            ulonglong2 q = *(const ulonglong2*)&Ws[cb][kk][tx*4];
            float a8[8] = {f0.x,f0.y,f0.z,f0.w,f1.x,f1.y,f1.z,f1.w};
            #pragma unroll
            for (int i = 0; i < 8; i++) {
                unsigned long long ad = pk2(a8[i], a8[i]);
                fma2(acc[i][0], ad, q.x);
                fma2(acc[i][1], ad, q.y);
            }
        }
        if (c + 1 < NIT) {
            const int nb = cb ^ 1;
            As[nb][lka+0][lr]=a0.x; As[nb][lka+1][lr]=a0.y; As[nb][lka+2][lr]=a0.z; As[nb][lka+3][lr]=a0.w;
            As[nb][lka+4][lr]=a1.x; As[nb][lka+5][lr]=a1.y; As[nb][lka+6][lr]=a1.z; As[nb][lka+7][lr]=a1.w;
            Ws[nb][wka+0][wr]=wv.x; Ws[nb][wka+1][wr]=wv.y; Ws[nb][wka+2][wr]=wv.z; Ws[nb][wka+3][wr]=wv.w;
        }
        __syncthreads();
    }

    const int n0 = bn + tx*4;
    #pragma unroll
    for (int i = 0; i < 8; i++) {
        int m = bm + ty*8 + i;
        float2 f0 = *(float2*)&acc[i][0];
        float2 f1 = *(float2*)&acc[i][1];
        float4 o = make_float4(f0.x, f0.y, f1.x, f1.y);
        if (mode == 1) {
            const int tt = m & (NT-1);
            const float* xr = xin + (size_t)m*NC + n0;
            float4 xv4 = *(const float4*)xr;
            float4 xp4 = make_float4(0.f,0.f,0.f,0.f);
            if (tt != 0) xp4 = *(const float4*)(xr - NC);
            float4 t4 = *(const float4*)(tmf + n0);
            o.x = fmaf(xp4.x - xv4.x, t4.x + o.x, xv4.x);
            o.y = fmaf(xp4.y - xv4.y, t4.y + o.y, xv4.y);
            o.z = fmaf(xp4.z - xv4.z, t4.z + o.z, xv4.z);
            o.w = fmaf(xp4.w - xv4.w, t4.w + o.w, xv4.w);
        }
        *(float4*)(C + (size_t)m*NC + n0) = o;
    }
}

__global__ __launch_bounds__(256, 2) void gemm_big_kernel(
    const float* __restrict__ A, int lda,
    const float* __restrict__ W, int ldw,
    float* __restrict__ C, int K)
{
    gemm_body(A, lda, W, ldw, C, K, 0, 0, 0);
}

__global__ __launch_bounds__(256, 2) void gemm_rkv_kernel(
    const float* __restrict__ A0, const float* __restrict__ A1, const float* __restrict__ A2,
    const float* __restrict__ W0, const float* __restrict__ W1, const float* __restrict__ W2,
    float* __restrict__ C0, float* __restrict__ C1, float* __restrict__ C2)
{
    const int z = blockIdx.z;
    const float* A = (z == 0) ? A0 : (z == 1) ? A1 : A2;
    const float* W = (z == 0) ? W0 : (z == 1) ? W1 : W2;
    float*       C = (z == 0) ? C0 : (z == 1) ? C1 : C2;
    gemm_body(A, NC, W, NC, C, NC, 0, 0, 0);
}

__global__ __launch_bounds__(256, 2) void gemm_mix4_kernel(
    const float* __restrict__ mixh, const float* __restrict__ maaw2,
    float* __restrict__ C0, float* __restrict__ C1,
    float* __restrict__ C2, float* __restrict__ C3,
    const float* __restrict__ x, const float* __restrict__ tm)
{
    const int z = blockIdx.z;
    float* C = (z == 0) ? C0 : (z == 1) ? C1 : (z == 2) ? C2 : C3;
    gemm_body(mixh + z*32, 128, maaw2 + (size_t)z*NC*32, 32, C, 32, x, tm + z*NC, 1);
}

__global__ __launch_bounds__(256, 2) void gemm_d4_kernel(
    const float* __restrict__ A0, const float* __restrict__ A1,
    const float* __restrict__ A2, const float* __restrict__ A3,
    const float* __restrict__ W0, const float* __restrict__ W1,
    const float* __restrict__ W2, const float* __restrict__ W3,
    float* __restrict__ C0, float* __restrict__ C1,
    float* __restrict__ C2, float* __restrict__ C3)
{
    const int z = blockIdx.z;
    const float* A = (z == 0) ? A0 : (z == 1) ? A1 : (z == 2) ? A2 : A3;
    const float* W = (z == 0) ? W0 : (z == 1) ? W1 : (z == 2) ? W2 : W3;
    float*       C = (z == 0) ? C0 : (z == 1) ? C1 : (z == 2) ? C2 : C3;
    gemm_body(A, 16, W, 16, C, 16, 0, 0, 0);
}

// ---------------- LORA GEMM v2: register-blocked 64x32 tile, K-split -------------
// Each of 128 threads computes 4m x 4n. Per k-step: 2x LDS.128 + 16 FMA.
// W rows [0,nb0)->W0, [nb0,nb1)->W1, [nb1,N)->W2.  smode 1: fused token shift.
__global__ __launch_bounds__(128) void lora_kernel(
    const float* __restrict__ A,
    const float* __restrict__ W0, const float* __restrict__ W1, const float* __restrict__ W2,
    int nb0, int nb1,
    float* __restrict__ part, int N, int K, int ks,
    int smode, const float* __restrict__ tmx)
{
    __shared__ __align__(16) float As[32][68];   // [k][m], 64 rows + pad
    __shared__ __align__(16) float Ws[32][36];   // [k][n]
    const int bm = blockIdx.x * 64;
    const int bn = blockIdx.y * 32;
    const int kb = blockIdx.z;
    const int klen = K / ks;
    const int kbeg = kb * klen;
    const int tid = threadIdx.x;
    const int ty = tid >> 3;        // 0..15 -> m-group of 4
    const int tx = tid & 7;         // 0..7  -> n-group of 4

    float acc[4][4];
    #pragma unroll
    for (int i = 0; i < 4; i++)
        #pragma unroll
        for (int j = 0; j < 4; j++) acc[i][j] = 0.f;

    for (int k0 = kbeg; k0 < kbeg + klen; k0 += 32) {
        // load A tile: 64 rows x 32 k = 512 float4; 4 per thread
        #pragma unroll
        for (int i = 0; i < 4; i++) {
            const int idx = tid + i*128;
            const int row = idx >> 3;
            const int kq  = idx & 7;
            float4 av;
            if (smode) {
                const int m = bm + row;
                const int tt = m & (NT-1);
                const float* xr = A + (size_t)m*K + k0 + kq*4;
                float4 xv4 = *(const float4*)xr;
                float4 xp4 = make_float4(0.f,0.f,0.f,0.f);
                if (tt != 0) xp4 = *(const float4*)(xr - K);
                float4 t4 = *(const float4*)(tmx + k0 + kq*4);
                av.x = fmaf(xp4.x - xv4.x, t4.x, xv4.x);
                av.y = fmaf(xp4.y - xv4.y, t4.y, xv4.y);
                av.z = fmaf(xp4.z - xv4.z, t4.z, xv4.z);
                av.w = fmaf(xp4.w - xv4.w, t4.w, xv4.w);
            } else {
                av = *(const float4*)(A + (size_t)(bm+row)*K + k0 + kq*4);
            }
            As[kq*4+0][row]=av.x; As[kq*4+1][row]=av.y;
            As[kq*4+2][row]=av.z; As[kq*4+3][row]=av.w;
        }
        // load W tile: 32 rows x 32 k = 256 float4; 2 per thread
        #pragma unroll
        for (int i = 0; i < 2; i++) {
            const int idx = tid + i*128;
            const int row = idx >> 3;
            const int kq  = idx & 7;
            const int wrow = bn + row;
            const float* wp;
            if (wrow < nb0)      wp = W0 + (size_t)wrow*K;
            else if (wrow < nb1) wp = W1 + (size_t)(wrow - nb0)*K;
            else                 wp = W2 + (size_t)(wrow - nb1)*K;
            float4 wv = *(const float4*)(wp + k0 + kq*4);
            Ws[kq*4+0][row]=wv.x; Ws[kq*4+1][row]=wv.y;
            Ws[kq*4+2][row]=wv.z; Ws[kq*4+3][row]=wv.w;
        }
        __syncthreads();
        #pragma unroll
        for (int kk = 0; kk < 32; kk++) {
            float4 a4 = *(const float4*)&As[kk][ty*4];
            float4 w4 = *(const float4*)&Ws[kk][tx*4];
            float am[4] = {a4.x, a4.y, a4.z, a4.w};
            #pragma unroll
            for (int i = 0; i < 4; i++) {
                acc[i][0] = fmaf(am[i], w4.x, acc[i][0]);
                acc[i][1] = fmaf(am[i], w4.y, acc[i][1]);
                acc[i][2] = fmaf(am[i], w4.z, acc[i][2]);
                acc[i][3] = fmaf(am[i], w4.w, acc[i][3]);
            }
        }
        __syncthreads();
    }
    const int n0 = bn + tx*4;
    #pragma unroll
    for (int i = 0; i < 4; i++) {
        const int m = bm + ty*4 + i;
        float* pr = part + ((size_t)kb*NBT + m)*N;
        *(float4*)(pr + n0) = make_float4(acc[i][0], acc[i][1], acc[i][2], acc[i][3]);
    }
}

// reduce ks partials (float4), apply per-range tanh, scatter to up to 3 dests.
__global__ __launch_bounds__(256) void lora_reduce_kernel(
    const float* __restrict__ part, int N, int ks,
    float* __restrict__ d0, int n0, int act0,
    float* __restrict__ d1, int n1, int act1,
    float* __restrict__ d2, int n2, int act2)
{
    const int idx = blockIdx.x*256 + threadIdx.x;
    const int n4 = N >> 2;
    const int m = idx / n4;
    const int c = (idx - m*n4) << 2;
    float4 s = make_float4(0.f,0.f,0.f,0.f);
    for (int z = 0; z < ks; z++) {
        float4 p = *(const float4*)(part + ((size_t)z*NBT + m)*N + c);
        s.x += p.x; s.y += p.y; s.z += p.z; s.w += p.w;
    }
    float* d; int act;
    if (c < n0)           { d = d0 + (size_t)m*n0 + c;            act = act0; }
    else if (c < n0 + n1) { d = d1 + (size_t)m*n1 + (c - n0);     act = act1; }
    else                  { d = d2 + (size_t)m*n2 + (c - n0 - n1); act = act2; }
    if (act) { s.x = tanhf(s.x); s.y = tanhf(s.y); s.z = tanhf(s.z); s.w = tanhf(s.w); }
    *(float4*)d = s;
}

// ---------------- post ----------------
__global__ __launch_bounds__(256) void post_kernel(
    const float* __restrict__ td,  const float* __restrict__ ta5,
    const float* __restrict__ tma_, const float* __restrict__ tmk_)
{
    const int tok = blockIdx.x;
    const int tid = threadIdx.x;
    const size_t base = (size_t)tok*NC;
    const int c = tid * 4;
    float4 kraw = *(const float4*)(g_k   + base + c);
    float4 dw4  = *(const float4*)(g_dw  + base + c);
    float4 da4  = *(const float4*)(g_da  + base + c);
    float4 dma4 = *(const float4*)(g_dma + base + c);
    float4 dkk4 = *(const float4*)(g_dkk + base + c);
    float4 dmk4 = *(const float4*)(g_dmk + base + c);
    float4 td4  = *(const float4*)(td   + c);
    float4 ta4  = *(const float4*)(ta5  + c);
    float4 tm4  = *(const float4*)(tma_ + c);
    float4 tk4  = *(const float4*)(tmk_ + c);

    float kr[4] = {kraw.x, kraw.y, kraw.z, kraw.w};
    float uw[4] = {td4.x+dw4.x, td4.y+dw4.y, td4.z+dw4.z, td4.w+dw4.w};
    float ua[4] = {ta4.x+da4.x, ta4.y+da4.y, ta4.z+da4.z, ta4.w+da4.w};
    float um[4] = {tm4.x+dma4.x, tm4.y+dma4.y, tm4.z+dma4.z, tm4.w+dma4.w};
    float uk[4] = {tk4.x+dmk4.x, tk4.y+dmk4.y, tk4.z+dmk4.z, tk4.w+dmk4.w};
    float kkq[4] = {kr[0]+dkk4.x, kr[1]+dkk4.y, kr[2]+dkk4.z, kr[3]+dkk4.w};

    float ewv[4], kfv[4], avv[4];
    float ss = 0.f;
    #pragma unroll
    for (int q = 0; q < 4; q++) {
        float spz = -uw[q];
        float sp = (spz > 15.f) ? spz : log1pf(expf(spz));
        float w = -sp - 0.5f;
        ewv[q] = expf(w);
        float a  = 1.f/(1.f + expf(-ua[q]));
        float ma = 1.f/(1.f + expf(-um[q]));
        float mk = 1.f/(1.f + expf(-uk[q]));
        avv[q] = a;
        kfv[q] = kr[q] * (ma + a*(1.f - ma)) * expf(w*mk);
        ss = fmaf(kkq[q], kkq[q], ss);
    }
    ss += __shfl_xor_sync(0xffffffffu, ss, 1);
    ss += __shfl_xor_sync(0xffffffffu, ss, 2);
    ss += __shfl_xor_sync(0xffffffffu, ss, 4);
    ss += __shfl_xor_sync(0xffffffffu, ss, 8);
    const float rinv = 1.f / fmaxf(sqrtf(ss), 1e-12f);
    float4 kkn4, bb4, ew4, kf4;
    kkn4.x = kkq[0]*rinv; kkn4.y = kkq[1]*rinv; kkn4.z = kkq[2]*rinv; kkn4.w = kkq[3]*rinv;
    bb4.x = -kkn4.x*avv[0]; bb4.y = -kkn4.y*avv[1]; bb4.z = -kkn4.z*avv[2]; bb4.w = -kkn4.w*avv[3];
    ew4.x = ewv[0]; ew4.y = ewv[1]; ew4.z = ewv[2]; ew4.w = ewv[3];
    kf4.x = kfv[0]; kf4.y = kfv[1]; kf4.z = kfv[2]; kf4.w = kfv[3];
    *(float4*)(g_kkn + base + c) = kkn4;
    *(float4*)(g_bb  + base + c) = bb4;
    *(float4*)(g_ew  + base + c) = ew4;
    *(float4*)(g_kf  + base + c) = kf4;
}

// ---------------- RWKV-7 scan ----------------
#define LOAD_ARR(arr, G) { \
    const int i0 = tid, i1 = tid + 128; \
    pf[2*(arr)+0] = *(const float4*)((G) + gb + (size_t)(i0>>4)*NC + ((i0&15)<<2)); \
    pf[2*(arr)+1] = *(const float4*)((G) + gb + (size_t)(i1>>4)*NC + ((i1&15)<<2)); }
#define STORE_ARR(arr, dst) { \
    const int i0 = tid, i1 = tid + 128; \
    *(float4*)&cbuf[dst][arr][i0>>4][(i0&15)<<2] = pf[2*(arr)+0]; \
    *(float4*)&cbuf[dst][arr][i1>>4][(i1&15)<<2] = pf[2*(arr)+1]; }

__global__ __launch_bounds__(128) void scan_kernel()
{
    const int blk = blockIdx.x;
    const int bh  = blk >> 1;
    const int rh  = blk & 1;
    const int b   = bh >> 4;
    const int h   = bh & 15;
    const int tid = threadIdx.x;
    const int row = rh*32 + (tid >> 2);
    const int sub = tid & 3;
    const int coff = sub * 16;

    __shared__ __align__(16) float cbuf[2][6][CH][64];

    unsigned long long S[8];
    #pragma unroll
    for (int j = 0; j < 8; j++) S[j] = 0ull;

    const size_t base = ((size_t)b*NT)*NC + (size_t)h*NNh;

    {
        const size_t gb = base;
        float4 pf[12];
        LOAD_ARR(0, g_r);  LOAD_ARR(1, g_ew); LOAD_ARR(2, g_kf);
        LOAD_ARR(3, g_v);  LOAD_ARR(4, g_kkn); LOAD_ARR(5, g_bb);
        STORE_ARR(0, 0); STORE_ARR(1, 0); STORE_ARR(2, 0);
        STORE_ARR(3, 0); STORE_ARR(4, 0); STORE_ARR(5, 0);
    }
    __syncthreads();

    for (int c = 0; c < NCH; c++) {
        const int buf = c & 1;
        const int nb  = buf ^ 1;
        float4 pf[12];
        if (c + 1 < NCH) {
            const size_t gb = base + (size_t)((c+1)*CH)*NC;
            LOAD_ARR(0, g_r);  LOAD_ARR(1, g_ew); LOAD_ARR(2, g_kf);
            LOAD_ARR(3, g_v);  LOAD_ARR(4, g_kkn); LOAD_ARR(5, g_bb);
        }
        const size_t ybase = base + (size_t)(c*CH)*NC + row;
        #pragma unroll 4
        for (int s = 0; s < CH; s++) {
            const ulonglong2* rp  = (const ulonglong2*)&cbuf[buf][0][s][coff];
            const ulonglong2* ewp = (const ulonglong2*)&cbuf[buf][1][s][coff];
            const ulonglong2* kfp = (const ulonglong2*)&cbuf[buf][2][s][coff];
            const ulonglong2* kkp = (const ulonglong2*)&cbuf[buf][4][s][coff];
            const ulonglong2* bbp = (const ulonglong2*)&cbuf[buf][5][s][coff];
            const float vv = cbuf[buf][3][s][row];
            unsigned long long a0 = 0ull, a1 = 0ull;
            #pragma unroll
            for (int j = 0; j < 4; j++) {
                ulonglong2 kq = kkp[j];
                fma2(a0, S[2*j+0], kq.x);
                fma2(a1, S[2*j+1], kq.y);
            }
            float2 fa0 = up2(a0), fa1 = up2(a1);
            float sab = (fa0.x + fa0.y) + (fa1.x + fa1.y);
            sab += __shfl_xor_sync(0xffffffffu, sab, 1);
            sab += __shfl_xor_sync(0xffffffffu, sab, 2);
            const unsigned long long sab2 = pk2(sab, sab);
            const unsigned long long vv2  = pk2(vv, vv);
            unsigned long long y0 = 0ull, y1 = 0ull;
            #pragma unroll
            for (int j = 0; j < 4; j++) {
                ulonglong2 eq = ewp[j], bq = bbp[j], kq = kfp[j], rq = rp[j];
                unsigned long long t0 = mul2(S[2*j+0], eq.x);
                fma2(t0, sab2, bq.x);
                fma2(t0, vv2,  kq.x);
                S[2*j+0] = t0;
                fma2(y0, t0, rq.x);
                unsigned long long t1 = mul2(S[2*j+1], eq.y);
                fma2(t1, sab2, bq.y);
                fma2(t1, vv2,  kq.y);
                S[2*j+1] = t1;
                fma2(y1, t1, rq.y);
            }
            float2 fy0 = up2(y0), fy1 = up2(y1);
            float yv = (fy0.x + fy0.y) + (fy1.x + fy1.y);
            yv += __shfl_xor_sync(0xffffffffu, yv, 1);
            yv += __shfl_xor_sync(0xffffffffu, yv, 2);
            if (sub == 0) g_y[ybase + (size_t)s*NC] = yv;
        }
        if (c + 1 < NCH) {
            STORE_ARR(0, nb); STORE_ARR(1, nb); STORE_ARR(2, nb);
            STORE_ARR(3, nb); STORE_ARR(4, nb); STORE_ARR(5, nb);
        }
        __syncthreads();
    }
}

// ---------------- tail ----------------
__global__ __launch_bounds__(256) void tail_kernel(
    const float* __restrict__ lnw, const float* __restrict__ lnb,
    const float* __restrict__ faaaa)
{
    const int tok = blockIdx.x;
    const int tid = threadIdx.x;
    const size_t base = (size_t)tok*NC;
    float yv[4], vv[4];
    float sy=0.f, syy=0.f, srk=0.f;
    #pragma unroll
    for (int q = 0; q < 4; q++) {
        const int c = tid*4 + q;
        float y = g_y[base+c];
        float r = g_r[base+c];
        float k = g_kf[base+c];
        vv[q] = g_v[base+c];
        yv[q] = y;
        sy += y;
        syy = fmaf(y, y, syy);
        srk = fmaf(r*k, faaaa[c], srk);
    }
    #pragma unroll
    for (int o = 1; o < 16; o <<= 1) {
        sy  += __shfl_xor_sync(0xffffffffu, sy,  o);
        syy += __shfl_xor_sync(0xffffffffu, syy, o);
        srk += __shfl_xor_sync(0xffffffffu, srk, o);
    }
    const float mu  = sy * (1.f/64.f);
    const float var = syy * (1.f/64.f) - mu*mu;
    const float inv = 1.f / sqrtf(var + 0.00064f);
    #pragma unroll
    for (int q = 0; q < 4; q++) {
        const int c = tid*4 + q;
        float yn = (yv[q] - mu) * inv * lnw[c] + lnb[c];
        g_z[base+c] = (yn + srk*vv[q]) * g_g[base+c];
    }
}

// ---------------- host ----------------
static inline void launch_big(const float* A, int lda, const float* W, int ldw,
                              float* C, int M, int K)
{
    dim3 grid(NC/64, M/128);
    gemm_big_kernel<<<grid, 256>>>(A, lda, W, ldw, C, K);
}
static inline void launch_lora(const float* A,
                               const float* W0, const float* W1, const float* W2,
                               int nb0, int nb1, float* part, int N, int K, int ks,
                               int smode, const float* tmx)
{
    dim3 grid(NBT/64, N/32, ks);
    lora_kernel<<<grid, 128>>>(A, W0, W1, W2, nb0, nb1, part, N, K, ks, smode, tmx);
}
static inline void launch_reduce(const float* part, int N, int ks,
                                 float* d0, int n0, int a0,
                                 float* d1, int n1, int a1,
                                 float* d2, int n2, int a2)
{
    lora_reduce_kernel<<<(NBT*N/4)/256, 256>>>(part, N, ks, d0, n0, a0, d1, n1, a1, d2, n2, a2);
}

extern "C" void kernel_launch(void* const* d_in, const int* in_sizes, int n_in,
                              void* d_out, int out_size)
{
    const float* x     = (const float*)d_in[0];
    const float* tmx   = (const float*)d_in[1];
    const float* tm    = (const float*)d_in[2];
    const float* maaw1 = (const float*)d_in[3];
    const float* maaw2 = (const float*)d_in[4];
    const float* td    = (const float*)d_in[5];
    const float* tdw1  = (const float*)d_in[6];
    const float* tdw2  = (const float*)d_in[7];
    const float* ta5   = (const float*)d_in[8];
    const float* taw1  = (const float*)d_in[9];
    const float* taw2  = (const float*)d_in[10];
    const float* tkw1  = (const float*)d_in[11];
    const float* tkw2  = (const float*)d_in[12];
    const float* gw1   = (const float*)d_in[13];
    const float* gw2   = (const float*)d_in[14];
    const float* tma_  = (const float*)d_in[15];
    const float* maw1  = (const float*)d_in[16];
    const float* maw2  = (const float*)d_in[17];
    const float* tmk_  = (const float*)d_in[18];
    const float* mkw1  = (const float*)d_in[19];
    const float* mkw2  = (const float*)d_in[20];
    const float* recw  = (const float*)d_in[21];
    const float* keyw  = (const float*)d_in[22];
    const float* valw  = (const float*)d_in[23];
    const float* outw  = (const float*)d_in[24];
    const float* lnw   = (const float*)d_in[25];
    const float* lnb   = (const float*)d_in[26];
    const float* faaaa = (const float*)d_in[27];
    float* out = (float*)d_out;

    float *p_mixh, *p_xrg, *p_xwa, *p_xk, *p_xv;
    float *p_r, *p_k, *p_v, *p_w1t, *p_a1, *p_ma1, *p_kk1, *p_mk1, *p_g1, *p_g, *p_z;
    float *p_dw, *p_da, *p_dma, *p_dkk, *p_dmk, *p_part;
    cudaGetSymbolAddress((void**)&p_mixh, g_mixh);
    cudaGetSymbolAddress((void**)&p_xrg,  g_xrg);
    cudaGetSymbolAddress((void**)&p_xwa,  g_xwa);
    cudaGetSymbolAddress((void**)&p_xk,   g_xk);
    cudaGetSymbolAddress((void**)&p_xv,   g_xv);
    cudaGetSymbolAddress((void**)&p_r,    g_r);
    cudaGetSymbolAddress((void**)&p_k,    g_k);
    cudaGetSymbolAddress((void**)&p_v,    g_v);
    cudaGetSymbolAddress((void**)&p_w1t,  g_w1t);
    cudaGetSymbolAddress((void**)&p_a1,   g_a1);
    cudaGetSymbolAddress((void**)&p_ma1,  g_ma1);
    cudaGetSymbolAddress((void**)&p_kk1,  g_kk1);
    cudaGetSymbolAddress((void**)&p_mk1,  g_mk1);
    cudaGetSymbolAddress((void**)&p_g1,   g_g1);
    cudaGetSymbolAddress((void**)&p_g,    g_g);
    cudaGetSymbolAddress((void**)&p_z,    g_z);
    cudaGetSymbolAddress((void**)&p_dw,   g_dw);
    cudaGetSymbolAddress((void**)&p_da,   g_da);
    cudaGetSymbolAddress((void**)&p_dma,  g_dma);
    cudaGetSymbolAddress((void**)&p_dkk,  g_dkk);
    cudaGetSymbolAddress((void**)&p_dmk,  g_dmk);
    cudaGetSymbolAddress((void**)&p_part, g_part);

    // 1. mix hidden: K-split lora + reduce(tanh)  (token shift fused into A-load)
    launch_lora(x, maaw1, maaw1, maaw1, 128, 128, p_part, 128, NC, 8, 1, tmx);
    launch_reduce(p_part, 128, 8, p_mixh, 128, 1, p_mixh, 0, 0, p_mixh, 0, 0);
    // 2. merged 4-way mixing (K=32, fused shift epilogue)
    {
        dim3 grid(NC/64, NBT/128, 4);
        gemm_mix4_kernel<<<grid, 256>>>(p_mixh, maaw2, p_xrg, p_xwa, p_xk, p_xv, x, tm);
    }
    // 3. xwa-cat LoRA hiddens: [w1t(64,tanh) | a1(16) | ma1(16)]
    launch_lora(p_xwa, tdw1, taw1, maw1, 64, 80, p_part, 96, NC, 8, 0, 0);
    launch_reduce(p_part, 96, 8, p_w1t, 64, 1, p_a1, 16, 0, p_ma1, 16, 0);
    // 4. merged r/k/v projections (K=1024)
    {
        dim3 grid(NC/64, NBT/128, 3);
        gemm_rkv_kernel<<<grid, 256>>>(p_xrg, p_xk, p_xv, recw, keyw, valw, p_r, p_k, p_v);
    }
    // 5. xk-cat LoRA hiddens: [kk1(16,tanh) | mk1(16)]
    launch_lora(p_xk, tkw1, mkw1, mkw1, 16, 32, p_part, 32, NC, 8, 0, 0);
    launch_reduce(p_part, 32, 8, p_kk1, 16, 1, p_mk1, 16, 0, p_mk1, 0, 0);
    // 6. gate hidden g1 (N=128, tanh)
    launch_lora(p_xrg, gw1, gw1, gw1, 128, 128, p_part, 128, NC, 8, 0, 0);
    launch_reduce(p_part, 128, 8, p_g1, 128, 1, p_g1, 0, 0, p_g1, 0, 0);
    // 7. gate g = g1 @ gate_w2^T (K=128)
    launch_big(p_g1, 128, gw2, 128, p_g, NBT, 128);
    // 8. dw (K=64)
    launch_big(p_w1t, 64, tdw2, 64, p_dw, NBT, 64);
    // 9. merged 4x K=16 delta GEMMs
    {
        dim3 grid(NC/64, NBT/128, 4);
        gemm_d4_kernel<<<grid, 256>>>(p_a1, p_ma1, p_kk1, p_mk1,
                                      taw2, maw2, tkw2, mkw2,
                                      p_da, p_dma, p_dkk, p_dmk);
    }
    // 10. elementwise post
    post_kernel<<<NBT, 256>>>(td, ta5, tma_, tmk_);
    // 11. RWKV-7 scan
    scan_kernel<<<NB*NH*2, 128>>>();
    // 12. GroupNorm + bonus + gate
    tail_kernel<<<NBT, 256>>>(lnw, lnb, faaaa);
    // 13. output projection
    launch_big(p_z, NC, outw, NC, out, NBT, NC);

    (void)in_sizes; (void)n_in; (void)out_size; (void)tdw1;
}